// round 6
// baseline (speedup 1.0000x reference)
#include <cuda_runtime.h>
#include <cuda_bf16.h>
#include <cstdint>

// Problem constants
#define BB 32
#define NN 400
#define TT 315
#define DD 512
#define HH 256
#define BT (BB*TT)          // 10080
#define NT (NN*TT)          // 126000

// ---------------- scratch (static device globals; no allocation) -------------
__device__ float g_WhT[HH*2*DD];        // [256][1024]
__device__ float g_TAT[TT*DD];          // [315][512]
__device__ float g_S[BB*NN*TT];         // [32][400][315]
__device__ float g_txh[TT*HH];          // [315][256]
__device__ float g_mv[2*BB];            // mean, rstd per batch
__device__ float g_part[BB*4*2];        // stats partials
__device__ float g_FWT[BB*HH*NN];       // [32][256][400]
__device__ float g_s1T[BB*TT*NN];       // [32][315][400]
__device__ float g_H[BB*TT*HH];         // [32][315][256]

// ================= helpers ===================================================
__device__ __forceinline__ uint32_t smem_to_u32(const void* p) {
    uint32_t a;
    asm("{ .reg .u64 t; cvta.to.shared.u64 t, %1; cvt.u32.u64 %0, t; }"
        : "=r"(a) : "l"(p));
    return a;
}

#define STS128(r0, r1, r2, r3, smem_addr) \
    asm volatile("st.shared.v4.b32 [%0], {%1, %2, %3, %4};" \
        :: "r"(smem_addr), "r"(r0), "r"(r1), "r"(r2), "r"(r3) : "memory")

#define MBARRIER_INIT(addr, cnt) \
    asm volatile("mbarrier.init.shared.b64 [%0], %1;" \
        :: "r"((uint32_t)(addr)), "r"((uint32_t)(cnt)) : "memory")

// remote arrive on peer CTA's mbarrier (same smem offset), release/cluster
#define MBAR_ARRIVE_REMOTE(local_mbar_addr, target_rank) \
    asm volatile("{\n\t.reg .b32 ra;\n\t" \
        "mapa.shared::cluster.u32 ra, %0, %1;\n\t" \
        "mbarrier.arrive.release.cluster.shared::cluster.b64 _, [ra];\n\t}" \
        :: "r"((uint32_t)(local_mbar_addr)), "r"((uint32_t)(target_rank)) : "memory")

// parity wait with cluster-scope acquire
#define MBAR_WAIT_CLUSTER(mbar_smem_addr, phase_parity) do { \
    uint32_t _mbar = (uint32_t)(mbar_smem_addr); \
    uint32_t _parity = (uint32_t)(phase_parity); \
    uint32_t _done; \
    asm volatile( \
        "{\n\t.reg .pred p;\n\t" \
        "mbarrier.try_wait.parity.acquire.cluster.shared::cta.b64 p, [%1], %2;\n\t" \
        "selp.b32 %0, 1, 0, p;\n\t}" \
        : "=r"(_done) : "r"(_mbar), "r"(_parity) : "memory"); \
    if (!_done) { \
        asm volatile( \
            "{\n\t.reg .pred P1;\n\t" \
            "WAIT_LOOP_%=:\n\t" \
            "mbarrier.try_wait.parity.acquire.cluster.shared::cta.b64 P1, [%0], %1, 0x989680;\n\t" \
            "@P1 bra.uni WAIT_DONE_%=;\n\t" \
            "bra.uni WAIT_LOOP_%=;\n\t" \
            "WAIT_DONE_%=:\n\t}" \
            :: "r"(_mbar), "r"(_parity) : "memory"); \
    } \
} while(0)

// split fp32 pair -> (hi bf16x2, lo bf16x2)
__device__ __forceinline__ void split2(float a0, float a1, uint32_t &h, uint32_t &l)
{
    asm("cvt.rn.satfinite.bf16x2.f32 %0, %1, %2;" : "=r"(h) : "f"(a1), "f"(a0));
    float h0 = __uint_as_float(h << 16);
    float h1 = __uint_as_float(h & 0xffff0000u);
    float l0 = a0 - h0;
    float l1 = a1 - h1;
    asm("cvt.rn.satfinite.bf16x2.f32 %0, %1, %2;" : "=r"(l) : "f"(l1), "f"(l0));
}

__device__ __forceinline__ void ldsm_x4(uint32_t* r, uint32_t addr) {
    asm volatile("ldmatrix.sync.aligned.m8n8.x4.shared.b16 {%0,%1,%2,%3}, [%4];"
        : "=r"(r[0]), "=r"(r[1]), "=r"(r[2]), "=r"(r[3]) : "r"(addr));
}

__device__ __forceinline__ void mma16816(float* c, const uint32_t* a, uint32_t b0, uint32_t b1) {
    asm volatile(
        "mma.sync.aligned.m16n8k16.row.col.f32.bf16.bf16.f32 "
        "{%0,%1,%2,%3}, {%4,%5,%6,%7}, {%8,%9}, {%0,%1,%2,%3};"
        : "+f"(c[0]), "+f"(c[1]), "+f"(c[2]), "+f"(c[3])
        : "r"(a[0]), "r"(a[1]), "r"(a[2]), "r"(a[3]), "r"(b0), "r"(b1));
}

// ================= HMMA bf16-split NT GEMM (unchanged from R4) ===============
#define AS 80
#define APL (128*AS)
#define BPL (64*AS)
#define STG_SZ (2*APL + 2*BPL)
#define HG_SMEM (2*STG_SZ)

template<int EPI>
__global__ void __launch_bounds__(256, 2) hgemm(
    int M, int N, int K,
    const float* __restrict__ A, int lda, long long sA,
    const float* __restrict__ B, int ldb, long long sB,
    float* __restrict__ C, int ldc, long long sC,
    const float* __restrict__ aux, const float* __restrict__ bias)
{
    extern __shared__ char smem[];
    uint32_t sb = smem_to_u32(smem);
    int tid = threadIdx.x, lane = tid & 31, wid = tid >> 5;

    A += (long long)blockIdx.z * sA;
    B += (long long)blockIdx.z * sB;
    C += (long long)blockIdx.z * sC;
    int m0 = blockIdx.y * 128, n0 = blockIdx.x * 64;

    const int arow = tid >> 1, abase = (tid & 1) * 16;
    const bool aok = (m0 + arow) < M;
    const float* Arow = A + (size_t)(m0 + arow) * lda;
    const int brow = tid >> 2, bbase = (tid & 3) * 8;
    const bool bok = (n0 + brow) < N;
    const float* Brow = B + (size_t)(n0 + brow) * ldb;

    float acc[2][4][4];
    #pragma unroll
    for (int mi = 0; mi < 2; mi++)
        #pragma unroll
        for (int ni = 0; ni < 4; ni++)
            #pragma unroll
            for (int j = 0; j < 4; j++) acc[mi][ni][j] = 0.f;

    const int nst = (K + 31) >> 5;
    float apf[16], bpf[8];

    auto loadg = [&](int st) {
        int k0 = st << 5;
        #pragma unroll
        for (int g = 0; g < 4; g++) {
            int kg = k0 + abase + g * 4;
            float4 v = make_float4(0.f, 0.f, 0.f, 0.f);
            if (aok && kg < K) v = *(const float4*)(Arow + kg);
            apf[g*4+0] = v.x; apf[g*4+1] = v.y; apf[g*4+2] = v.z; apf[g*4+3] = v.w;
        }
        #pragma unroll
        for (int g = 0; g < 2; g++) {
            int kg = k0 + bbase + g * 4;
            float4 v = make_float4(0.f, 0.f, 0.f, 0.f);
            if (bok && kg < K) v = *(const float4*)(Brow + kg);
            bpf[g*4+0] = v.x; bpf[g*4+1] = v.y; bpf[g*4+2] = v.z; bpf[g*4+3] = v.w;
        }
    };

    auto stores = [&](int buf) {
        uint32_t baseA = sb + buf * STG_SZ;
        uint32_t baseB = baseA + 2 * APL;
        #pragma unroll
        for (int g2 = 0; g2 < 2; g2++) {
            uint32_t h[4], l[4];
            #pragma unroll
            for (int j = 0; j < 4; j++)
                split2(apf[g2*8 + 2*j], apf[g2*8 + 2*j + 1], h[j], l[j]);
            uint32_t off = (uint32_t)(arow * AS + (abase + g2 * 8) * 2);
            STS128(h[0], h[1], h[2], h[3], baseA + off);
            STS128(l[0], l[1], l[2], l[3], baseA + APL + off);
        }
        {
            uint32_t h[4], l[4];
            #pragma unroll
            for (int j = 0; j < 4; j++)
                split2(bpf[2*j], bpf[2*j + 1], h[j], l[j]);
            uint32_t off = (uint32_t)(brow * AS + bbase * 2);
            STS128(h[0], h[1], h[2], h[3], baseB + off);
            STS128(l[0], l[1], l[2], l[3], baseB + BPL + off);
        }
    };

    const int wm = (wid & 3) * 32;
    const int wn = (wid >> 2) * 32;
    const int lrow = lane & 15;
    const int lkof = (lane >> 4) * 8;

    auto compute = [&](int buf) {
        uint32_t baseAhi = sb + buf * STG_SZ;
        uint32_t baseAlo = baseAhi + APL;
        uint32_t baseBhi = baseAhi + 2 * APL;
        uint32_t baseBlo = baseBhi + BPL;
        #pragma unroll
        for (int ks = 0; ks < 2; ks++) {
            uint32_t kb = (uint32_t)((ks * 16 + lkof) * 2);
            uint32_t ahi[2][4], alo[2][4], bhi[2][4], blo[2][4];
            #pragma unroll
            for (int mi = 0; mi < 2; mi++) {
                uint32_t off = (uint32_t)((wm + mi * 16 + lrow) * AS) + kb;
                ldsm_x4(ahi[mi], baseAhi + off);
                ldsm_x4(alo[mi], baseAlo + off);
            }
            #pragma unroll
            for (int np = 0; np < 2; np++) {
                uint32_t off = (uint32_t)((wn + np * 16 + lrow) * AS) + kb;
                ldsm_x4(bhi[np], baseBhi + off);
                ldsm_x4(blo[np], baseBlo + off);
            }
            #pragma unroll
            for (int mi = 0; mi < 2; mi++)
                #pragma unroll
                for (int ni = 0; ni < 4; ni++) {
                    int np = ni >> 1, sel = ni & 1;
                    uint32_t bh0 = bhi[np][sel], bh1 = bhi[np][2 + sel];
                    uint32_t bl0 = blo[np][sel], bl1 = blo[np][2 + sel];
                    mma16816(acc[mi][ni], ahi[mi], bh0, bh1);
                    mma16816(acc[mi][ni], ahi[mi], bl0, bl1);
                    mma16816(acc[mi][ni], alo[mi], bh0, bh1);
                }
        }
    };

    loadg(0);
    stores(0);
    __syncthreads();
    for (int c = 0; c < nst; c++) {
        if (c + 1 < nst) loadg(c + 1);
        compute(c & 1);
        if (c + 1 < nst) stores((c + 1) & 1);
        __syncthreads();
    }

    #pragma unroll
    for (int mi = 0; mi < 2; mi++) {
        #pragma unroll
        for (int ni = 0; ni < 4; ni++) {
            int gm = m0 + wm + mi * 16 + (lane >> 2);
            int gn = n0 + wn + ni * 8 + (lane & 3) * 2;
            float* cc = acc[mi][ni];
            #pragma unroll
            for (int half = 0; half < 2; half++) {
                int r = gm + half * 8;
                if (r < M) {
                    #pragma unroll
                    for (int j = 0; j < 2; j++) {
                        int col = gn + j;
                        if (col < N) {
                            float v = cc[half * 2 + j];
                            if (EPI == 1)
                                v = fmaxf(v + aux[(size_t)r * N + col] + bias[col], 0.f);
                            C[(size_t)r * ldc + col] = v;
                        }
                    }
                }
            }
        }
    }
}

// ---------------- generic 32x32 tiled transpose ------------------------------
__global__ void transpose_k(const float* __restrict__ in, float* __restrict__ out,
                            int R, int C)
{
    __shared__ float tile[32][33];
    int c0 = blockIdx.x * 32, r0 = blockIdx.y * 32;
    int x = threadIdx.x, y = threadIdx.y;
    #pragma unroll
    for (int j = 0; j < 32; j += 8) {
        int r = r0 + y + j, c = c0 + x;
        tile[y + j][x] = (r < R && c < C) ? in[(size_t)r * C + c] : 0.f;
    }
    __syncthreads();
    #pragma unroll
    for (int j = 0; j < 32; j += 8) {
        int c = c0 + y + j, r = r0 + x;
        if (c < C && r < R) out[(size_t)c * R + r] = tile[x][y + j];
    }
}

// ---------------- instance-norm stats (2-stage) ------------------------------
__global__ void stats_part(const float* __restrict__ s, float* __restrict__ part)
{
    int x = blockIdx.x, b = blockIdx.y;
    const float4* p = (const float4*)(s + (size_t)b * NT + (size_t)x * 31500);
    float sum = 0.f, sq = 0.f;
    for (int i = threadIdx.x; i < 7875; i += 256) {
        float4 v = p[i];
        sum += v.x + v.y + v.z + v.w;
        sq  += v.x*v.x + v.y*v.y + v.z*v.z + v.w*v.w;
    }
    __shared__ float ssum[256], ssq[256];
    ssum[threadIdx.x] = sum; ssq[threadIdx.x] = sq;
    __syncthreads();
    for (int o = 128; o > 0; o >>= 1) {
        if (threadIdx.x < o) {
            ssum[threadIdx.x] += ssum[threadIdx.x + o];
            ssq[threadIdx.x]  += ssq[threadIdx.x + o];
        }
        __syncthreads();
    }
    if (threadIdx.x == 0) {
        part[(b * 4 + x) * 2 + 0] = ssum[0];
        part[(b * 4 + x) * 2 + 1] = ssq[0];
    }
}

__global__ void stats_comb(const float* __restrict__ part, float* __restrict__ mv)
{
    int b = threadIdx.x;
    if (b >= BB) return;
    float sum = 0.f, sq = 0.f;
    #pragma unroll
    for (int x = 0; x < 4; x++) {
        sum += part[(b * 4 + x) * 2 + 0];
        sq  += part[(b * 4 + x) * 2 + 1];
    }
    float m = sum / (float)NT;
    float var = sq / (float)NT - m * m;
    mv[2 * b] = m;
    mv[2 * b + 1] = rsqrtf(var + 1e-5f);
}

// ---------------- Sinkhorn v2: E register-resident, DSMEM mbarrier sync ------
// 4-CTA cluster per batch; 512 threads; warp w holds rows {w+16j, j=0..6}.
#define SK_THREADS 512
#define SK_NW 16
#define RPC 100
#define RTP 320            // stride for vS-aligned structures (even, float2-safe)
#define STP 321            // stage stride (conflict-free column reads)
#define JMAX 7

#define OFF_V    0                      // 320 floats (padded, zeros beyond TT)
#define OFF_U    320                    // 128
#define OFF_WACC 448                    // 16*RTP = 5120
#define OFF_RECV 5568                   // 2*4*RTP = 2560
#define OFF_MBAR 8128                   // 4 floats = 2 mbarriers (8B aligned)
#define OFF_STAGE 8132                  // RPC*STP = 32100
#define SK_FLOATS (OFF_STAGE + RPC*STP) // 40232
#define SK_SMEM  (SK_FLOATS*4)          // 160928 bytes

__global__ void __cluster_dims__(4, 1, 1) __launch_bounds__(SK_THREADS, 1)
sinkhorn_kernel(
    const float* __restrict__ s, const float* __restrict__ gamma,
    const float* __restrict__ beta, const float* __restrict__ mv,
    float* __restrict__ s1T)
{
    extern __shared__ float sm[];
    float* vS    = sm + OFF_V;
    float* uS    = sm + OFF_U;
    float* wacc  = sm + OFF_WACC;
    float* recv  = sm + OFF_RECV;
    float* stage = sm + OFF_STAGE;
    uint32_t mbar = smem_to_u32(sm + OFF_MBAR);

    int b = blockIdx.x >> 2;
    int rank = blockIdx.x & 3;
    int tid = threadIdx.x, wid = tid >> 5, lane = tid & 31;
    int rowbase = rank * RPC;

    if (tid == 0) { MBARRIER_INIT(mbar, 4); MBARRIER_INIT(mbar + 8, 4); }
    for (int c = tid; c < RTP; c += SK_THREADS) vS[c] = (c < TT) ? 1.f : 0.f;
    __syncthreads();
    // barriers + vS must be ready cluster-wide before first remote traffic
    asm volatile("barrier.cluster.arrive.aligned;" ::: "memory");
    asm volatile("barrier.cluster.wait.aligned;" ::: "memory");

    float m = mv[2 * b], rstd = mv[2 * b + 1];
    float g = gamma[0] * rstd, be = beta[0];
    const float* sb = s + (size_t)b * NT;

    // load E slab into registers: E[j][k] covers row (wid+16j), cols 64k+2lane(+1)
    float2 E[JMAX][5];
    #pragma unroll
    for (int j = 0; j < JMAX; j++) {
        int r = wid + 16 * j;
        bool rv = (r < RPC);
        const float* srow = sb + (size_t)(rowbase + (rv ? r : 0)) * TT;
        #pragma unroll
        for (int k = 0; k < 5; k++) {
            int c = 64 * k + 2 * lane;
            E[j][k].x = (rv && c     < TT) ? __expf(g * (srow[c]     - m) + be) : 0.f;
            E[j][k].y = (rv && c + 1 < TT) ? __expf(g * (srow[c + 1] - m) + be) : 0.f;
        }
    }

    for (int it = 0; it < 100; ++it) {
        int par = it & 1;
        // --- row phase ---
        float2 vv[5];
        #pragma unroll
        for (int k = 0; k < 5; k++)
            vv[k] = *(const float2*)&vS[64 * k + 2 * lane];
        float2 ca[5];
        #pragma unroll
        for (int k = 0; k < 5; k++) ca[k] = make_float2(0.f, 0.f);

        #pragma unroll
        for (int j = 0; j < JMAX; j++) {
            int r = wid + 16 * j;
            if (r < RPC) {
                float dot = 0.f;
                #pragma unroll
                for (int k = 0; k < 5; k++) {
                    dot = fmaf(E[j][k].x, vv[k].x, dot);
                    dot = fmaf(E[j][k].y, vv[k].y, dot);
                }
                #pragma unroll
                for (int o = 16; o > 0; o >>= 1)
                    dot += __shfl_xor_sync(0xffffffffu, dot, o);
                float uu = __fdividef(1.f, dot);
                if (lane == 0) uS[r] = uu;
                #pragma unroll
                for (int k = 0; k < 5; k++) {
                    ca[k].x = fmaf(uu, E[j][k].x, ca[k].x);
                    ca[k].y = fmaf(uu, E[j][k].y, ca[k].y);
                }
            }
        }
        #pragma unroll
        for (int k = 0; k < 5; k++)
            *(float2*)&wacc[wid * RTP + 64 * k + 2 * lane] = ca[k];
        __syncthreads();

        // --- CTA partial -> broadcast to 4 cluster CTAs ---
        for (int c = tid; c < TT; c += SK_THREADS) {
            float p = 0.f;
            #pragma unroll
            for (int w = 0; w < SK_NW; w++) p += wacc[w * RTP + c];
            float* dst = recv + (par * 4 + rank) * RTP + c;
            uint32_t laddr = (uint32_t)__cvta_generic_to_shared(dst);
            #pragma unroll
            for (int cta = 0; cta < 4; cta++) {
                uint32_t raddr;
                asm volatile("mapa.shared::cluster.u32 %0, %1, %2;"
                             : "=r"(raddr) : "r"(laddr), "r"(cta));
                asm volatile("st.shared::cluster.f32 [%0], %1;"
                             :: "r"(raddr), "f"(p) : "memory");
            }
        }
        __syncthreads();
        if (tid == 0) {
            uint32_t lb = mbar + ((it & 1) << 3);
            #pragma unroll
            for (int cta = 0; cta < 4; cta++) MBAR_ARRIVE_REMOTE(lb, cta);
        }
        MBAR_WAIT_CLUSTER(mbar + ((it & 1) << 3), (it >> 1) & 1);

        // --- col phase ---
        for (int c = tid; c < TT; c += SK_THREADS) {
            float sum = recv[(par * 4 + 0) * RTP + c] + recv[(par * 4 + 1) * RTP + c]
                      + recv[(par * 4 + 2) * RTP + c] + recv[(par * 4 + 3) * RTP + c];
            vS[c] = __fdividef(1.f, sum);
        }
        __syncthreads();
    }

    // --- epilogue: stage = E*u, then transposed coalesced write * v ----------
    #pragma unroll
    for (int j = 0; j < JMAX; j++) {
        int r = wid + 16 * j;
        if (r < RPC) {
            float uu = uS[r];
            #pragma unroll
            for (int k = 0; k < 5; k++) {
                int c = 64 * k + 2 * lane;
                stage[r * STP + c]     = E[j][k].x * uu;
                stage[r * STP + c + 1] = E[j][k].y * uu;
            }
        }
    }
    __syncthreads();
    float* outp = s1T + (size_t)b * TT * NN;
    for (int t = wid; t < TT; t += SK_NW) {
        float vt = vS[t];
        #pragma unroll
        for (int jj = 0; jj < 4; jj++) {
            int n = lane + 32 * jj;
            if (n < RPC)
                outp[(size_t)t * NN + rowbase + n] = stage[n * STP + t] * vt;
        }
    }
}

// ---------------- final head: pred[bt] = dot(h[bt,:], Wo) + bo ---------------
__global__ void final_head(const float* __restrict__ h, const float* __restrict__ Wo,
                           const float* __restrict__ bo, float* __restrict__ out)
{
    int row = blockIdx.x * 8 + (threadIdx.x >> 5);
    int lane = threadIdx.x & 31;
    if (row >= BT) return;
    const float* hr = h + (size_t)row * HH;
    float acc = 0.f;
    #pragma unroll
    for (int k = 0; k < HH / 32; k++)
        acc += hr[lane + 32 * k] * Wo[lane + 32 * k];
    #pragma unroll
    for (int o = 16; o > 0; o >>= 1)
        acc += __shfl_xor_sync(0xffffffffu, acc, o);
    if (lane == 0) out[row] = acc + bo[0];
}

// ---------------- launcher ---------------------------------------------------
extern "C" void kernel_launch(void* const* d_in, const int* in_sizes, int n_in,
                              void* d_out, int out_size)
{
    const float* features = (const float*)d_in[0];
    const float* text     = (const float*)d_in[1];
    const float* Amat     = (const float*)d_in[2];
    const float* gamma    = (const float*)d_in[3];
    const float* beta     = (const float*)d_in[4];
    const float* Wh       = (const float*)d_in[5];
    const float* bh       = (const float*)d_in[6];
    const float* Wo       = (const float*)d_in[7];
    const float* bo       = (const float*)d_in[8];
    float* out = (float*)d_out;

    float *WhT, *TAT, *S, *txh, *mv, *part, *FWT, *s1T, *Hb;
    cudaGetSymbolAddress((void**)&WhT,  g_WhT);
    cudaGetSymbolAddress((void**)&TAT,  g_TAT);
    cudaGetSymbolAddress((void**)&S,    g_S);
    cudaGetSymbolAddress((void**)&txh,  g_txh);
    cudaGetSymbolAddress((void**)&mv,   g_mv);
    cudaGetSymbolAddress((void**)&part, g_part);
    cudaGetSymbolAddress((void**)&FWT,  g_FWT);
    cudaGetSymbolAddress((void**)&s1T,  g_s1T);
    cudaGetSymbolAddress((void**)&Hb,   g_H);

    cudaFuncSetAttribute(sinkhorn_kernel,
                         cudaFuncAttributeMaxDynamicSharedMemorySize, SK_SMEM);
    cudaFuncSetAttribute(hgemm<0>,
                         cudaFuncAttributeMaxDynamicSharedMemorySize, HG_SMEM);
    cudaFuncSetAttribute(hgemm<1>,
                         cudaFuncAttributeMaxDynamicSharedMemorySize, HG_SMEM);

    // fork a side stream for the Wh-dependent branch
    cudaStream_t s1;
    cudaStreamCreateWithFlags(&s1, cudaStreamNonBlocking);
    cudaEvent_t e0, e1;
    cudaEventCreateWithFlags(&e0, cudaEventDisableTiming);
    cudaEventCreateWithFlags(&e1, cudaEventDisableTiming);
    cudaEventRecord(e0, 0);
    cudaStreamWaitEvent(s1, e0, 0);

    // ---- side branch (stream s1): WhT -> txh, FWT ----
    transpose_k<<<dim3(8, 32, 1), dim3(32, 8), 0, s1>>>(Wh, WhT, 2 * DD, HH);
    hgemm<0><<<dim3(4, 3, 1), 256, HG_SMEM, s1>>>(TT, HH, DD,
        text, DD, 0, WhT + DD, 2 * DD, 0, txh, HH, 0, nullptr, nullptr);
    hgemm<0><<<dim3(7, 2, BB), 256, HG_SMEM, s1>>>(HH, NN, DD,
        WhT, 2 * DD, 0,
        features, DD, (long long)NN * DD,
        FWT, NN, (long long)HH * NN, nullptr, nullptr);
    cudaEventRecord(e1, s1);

    // ---- main branch (stream 0): TAT -> S -> stats -> sinkhorn ----
    hgemm<0><<<dim3(8, 3, 1), 256, HG_SMEM>>>(TT, DD, DD,
        text, DD, 0, Amat, DD, 0, TAT, DD, 0, nullptr, nullptr);
    hgemm<0><<<dim3(5, 100, 1), 256, HG_SMEM>>>(BB * NN, TT, DD,
        features, DD, 0, TAT, DD, 0, S, TT, 0, nullptr, nullptr);
    stats_part<<<dim3(4, BB), 256>>>(S, part);
    stats_comb<<<1, 32>>>(part, mv);
    sinkhorn_kernel<<<BB * 4, SK_THREADS, SK_SMEM>>>(S, gamma, beta, mv, s1T);

    // join, then head
    cudaStreamWaitEvent(0, e1, 0);
    hgemm<1><<<dim3(4, 3, BB), 256, HG_SMEM>>>(TT, HH, NN,
        s1T, NN, (long long)TT * NN,
        FWT, NN, (long long)HH * NN,
        Hb,  HH, (long long)TT * HH, txh, bh);
    final_head<<<1260, 256>>>(Hb, Wo, bo, out);

    cudaEventDestroy(e0);
    cudaEventDestroy(e1);
    cudaStreamDestroy(s1);
}

// round 7
// speedup vs baseline: 1.5301x; 1.5301x over previous
#include <cuda_runtime.h>
#include <cuda_bf16.h>
#include <cstdint>

// Problem constants
#define BB 32
#define NN 400
#define TT 315
#define DD 512
#define HH 256
#define BT (BB*TT)          // 10080
#define NT (NN*TT)          // 126000

// ---------------- scratch (static device globals; no allocation) -------------
__device__ float g_WhT[HH*2*DD];        // [256][1024]
__device__ float g_TAT[TT*DD];          // [315][512]
__device__ float g_S[BB*NN*TT];         // [32][400][315]
__device__ float g_txh[TT*HH];          // [315][256]
__device__ float g_mv[2*BB];            // mean, rstd per batch
__device__ float g_part[BB*4*2];        // stats partials
__device__ float g_FWT[BB*HH*NN];       // [32][256][400]
__device__ float g_s1T[BB*TT*NN];       // [32][315][400]
__device__ float g_H[BB*TT*HH];         // [32][315][256]

// ================= helpers ===================================================
__device__ __forceinline__ uint32_t smem_to_u32(const void* p) {
    uint32_t a;
    asm("{ .reg .u64 t; cvta.to.shared.u64 t, %1; cvt.u32.u64 %0, t; }"
        : "=r"(a) : "l"(p));
    return a;
}

#define STS128(r0, r1, r2, r3, smem_addr) \
    asm volatile("st.shared.v4.b32 [%0], {%1, %2, %3, %4};" \
        :: "r"(smem_addr), "r"(r0), "r"(r1), "r"(r2), "r"(r3) : "memory")

#define MBARRIER_INIT(addr, cnt) \
    asm volatile("mbarrier.init.shared.b64 [%0], %1;" \
        :: "r"((uint32_t)(addr)), "r"((uint32_t)(cnt)) : "memory")

// remote arrive on peer CTA's mbarrier (same smem offset), release/cluster
#define MBAR_ARRIVE_REMOTE(local_mbar_addr, target_rank) \
    asm volatile("{\n\t.reg .b32 ra;\n\t" \
        "mapa.shared::cluster.u32 ra, %0, %1;\n\t" \
        "mbarrier.arrive.release.cluster.shared::cluster.b64 _, [ra];\n\t}" \
        :: "r"((uint32_t)(local_mbar_addr)), "r"((uint32_t)(target_rank)) : "memory")

// parity wait with cluster-scope acquire
#define MBAR_WAIT_CLUSTER(mbar_smem_addr, phase_parity) do { \
    uint32_t _mbar = (uint32_t)(mbar_smem_addr); \
    uint32_t _parity = (uint32_t)(phase_parity); \
    uint32_t _done; \
    asm volatile( \
        "{\n\t.reg .pred p;\n\t" \
        "mbarrier.try_wait.parity.acquire.cluster.shared::cta.b64 p, [%1], %2;\n\t" \
        "selp.b32 %0, 1, 0, p;\n\t}" \
        : "=r"(_done) : "r"(_mbar), "r"(_parity) : "memory"); \
    if (!_done) { \
        asm volatile( \
            "{\n\t.reg .pred P1;\n\t" \
            "WAIT_LOOP_%=:\n\t" \
            "mbarrier.try_wait.parity.acquire.cluster.shared::cta.b64 P1, [%0], %1, 0x989680;\n\t" \
            "@P1 bra.uni WAIT_DONE_%=;\n\t" \
            "bra.uni WAIT_LOOP_%=;\n\t" \
            "WAIT_DONE_%=:\n\t}" \
            :: "r"(_mbar), "r"(_parity) : "memory"); \
    } \
} while(0)

// split fp32 pair -> (hi bf16x2, lo bf16x2)
__device__ __forceinline__ void split2(float a0, float a1, uint32_t &h, uint32_t &l)
{
    asm("cvt.rn.satfinite.bf16x2.f32 %0, %1, %2;" : "=r"(h) : "f"(a1), "f"(a0));
    float h0 = __uint_as_float(h << 16);
    float h1 = __uint_as_float(h & 0xffff0000u);
    float l0 = a0 - h0;
    float l1 = a1 - h1;
    asm("cvt.rn.satfinite.bf16x2.f32 %0, %1, %2;" : "=r"(l) : "f"(l1), "f"(l0));
}

__device__ __forceinline__ void ldsm_x4(uint32_t* r, uint32_t addr) {
    asm volatile("ldmatrix.sync.aligned.m8n8.x4.shared.b16 {%0,%1,%2,%3}, [%4];"
        : "=r"(r[0]), "=r"(r[1]), "=r"(r[2]), "=r"(r[3]) : "r"(addr));
}

__device__ __forceinline__ void mma16816(float* c, const uint32_t* a, uint32_t b0, uint32_t b1) {
    asm volatile(
        "mma.sync.aligned.m16n8k16.row.col.f32.bf16.bf16.f32 "
        "{%0,%1,%2,%3}, {%4,%5,%6,%7}, {%8,%9}, {%0,%1,%2,%3};"
        : "+f"(c[0]), "+f"(c[1]), "+f"(c[2]), "+f"(c[3])
        : "r"(a[0]), "r"(a[1]), "r"(a[2]), "r"(a[3]), "r"(b0), "r"(b1));
}

// ================= HMMA bf16-split NT GEMM (unchanged from R4) ===============
#define AS 80
#define APL (128*AS)
#define BPL (64*AS)
#define STG_SZ (2*APL + 2*BPL)
#define HG_SMEM (2*STG_SZ)

template<int EPI>
__global__ void __launch_bounds__(256, 2) hgemm(
    int M, int N, int K,
    const float* __restrict__ A, int lda, long long sA,
    const float* __restrict__ B, int ldb, long long sB,
    float* __restrict__ C, int ldc, long long sC,
    const float* __restrict__ aux, const float* __restrict__ bias)
{
    extern __shared__ char smem[];
    uint32_t sb = smem_to_u32(smem);
    int tid = threadIdx.x, lane = tid & 31, wid = tid >> 5;

    A += (long long)blockIdx.z * sA;
    B += (long long)blockIdx.z * sB;
    C += (long long)blockIdx.z * sC;
    int m0 = blockIdx.y * 128, n0 = blockIdx.x * 64;

    const int arow = tid >> 1, abase = (tid & 1) * 16;
    const bool aok = (m0 + arow) < M;
    const float* Arow = A + (size_t)(m0 + arow) * lda;
    const int brow = tid >> 2, bbase = (tid & 3) * 8;
    const bool bok = (n0 + brow) < N;
    const float* Brow = B + (size_t)(n0 + brow) * ldb;

    float acc[2][4][4];
    #pragma unroll
    for (int mi = 0; mi < 2; mi++)
        #pragma unroll
        for (int ni = 0; ni < 4; ni++)
            #pragma unroll
            for (int j = 0; j < 4; j++) acc[mi][ni][j] = 0.f;

    const int nst = (K + 31) >> 5;
    float apf[16], bpf[8];

    auto loadg = [&](int st) {
        int k0 = st << 5;
        #pragma unroll
        for (int g = 0; g < 4; g++) {
            int kg = k0 + abase + g * 4;
            float4 v = make_float4(0.f, 0.f, 0.f, 0.f);
            if (aok && kg < K) v = *(const float4*)(Arow + kg);
            apf[g*4+0] = v.x; apf[g*4+1] = v.y; apf[g*4+2] = v.z; apf[g*4+3] = v.w;
        }
        #pragma unroll
        for (int g = 0; g < 2; g++) {
            int kg = k0 + bbase + g * 4;
            float4 v = make_float4(0.f, 0.f, 0.f, 0.f);
            if (bok && kg < K) v = *(const float4*)(Brow + kg);
            bpf[g*4+0] = v.x; bpf[g*4+1] = v.y; bpf[g*4+2] = v.z; bpf[g*4+3] = v.w;
        }
    };

    auto stores = [&](int buf) {
        uint32_t baseA = sb + buf * STG_SZ;
        uint32_t baseB = baseA + 2 * APL;
        #pragma unroll
        for (int g2 = 0; g2 < 2; g2++) {
            uint32_t h[4], l[4];
            #pragma unroll
            for (int j = 0; j < 4; j++)
                split2(apf[g2*8 + 2*j], apf[g2*8 + 2*j + 1], h[j], l[j]);
            uint32_t off = (uint32_t)(arow * AS + (abase + g2 * 8) * 2);
            STS128(h[0], h[1], h[2], h[3], baseA + off);
            STS128(l[0], l[1], l[2], l[3], baseA + APL + off);
        }
        {
            uint32_t h[4], l[4];
            #pragma unroll
            for (int j = 0; j < 4; j++)
                split2(bpf[2*j], bpf[2*j + 1], h[j], l[j]);
            uint32_t off = (uint32_t)(brow * AS + bbase * 2);
            STS128(h[0], h[1], h[2], h[3], baseB + off);
            STS128(l[0], l[1], l[2], l[3], baseB + BPL + off);
        }
    };

    const int wm = (wid & 3) * 32;
    const int wn = (wid >> 2) * 32;
    const int lrow = lane & 15;
    const int lkof = (lane >> 4) * 8;

    auto compute = [&](int buf) {
        uint32_t baseAhi = sb + buf * STG_SZ;
        uint32_t baseAlo = baseAhi + APL;
        uint32_t baseBhi = baseAhi + 2 * APL;
        uint32_t baseBlo = baseBhi + BPL;
        #pragma unroll
        for (int ks = 0; ks < 2; ks++) {
            uint32_t kb = (uint32_t)((ks * 16 + lkof) * 2);
            uint32_t ahi[2][4], alo[2][4], bhi[2][4], blo[2][4];
            #pragma unroll
            for (int mi = 0; mi < 2; mi++) {
                uint32_t off = (uint32_t)((wm + mi * 16 + lrow) * AS) + kb;
                ldsm_x4(ahi[mi], baseAhi + off);
                ldsm_x4(alo[mi], baseAlo + off);
            }
            #pragma unroll
            for (int np = 0; np < 2; np++) {
                uint32_t off = (uint32_t)((wn + np * 16 + lrow) * AS) + kb;
                ldsm_x4(bhi[np], baseBhi + off);
                ldsm_x4(blo[np], baseBlo + off);
            }
            #pragma unroll
            for (int mi = 0; mi < 2; mi++)
                #pragma unroll
                for (int ni = 0; ni < 4; ni++) {
                    int np = ni >> 1, sel = ni & 1;
                    uint32_t bh0 = bhi[np][sel], bh1 = bhi[np][2 + sel];
                    uint32_t bl0 = blo[np][sel], bl1 = blo[np][2 + sel];
                    mma16816(acc[mi][ni], ahi[mi], bh0, bh1);
                    mma16816(acc[mi][ni], ahi[mi], bl0, bl1);
                    mma16816(acc[mi][ni], alo[mi], bh0, bh1);
                }
        }
    };

    loadg(0);
    stores(0);
    __syncthreads();
    for (int c = 0; c < nst; c++) {
        if (c + 1 < nst) loadg(c + 1);
        compute(c & 1);
        if (c + 1 < nst) stores((c + 1) & 1);
        __syncthreads();
    }

    #pragma unroll
    for (int mi = 0; mi < 2; mi++) {
        #pragma unroll
        for (int ni = 0; ni < 4; ni++) {
            int gm = m0 + wm + mi * 16 + (lane >> 2);
            int gn = n0 + wn + ni * 8 + (lane & 3) * 2;
            float* cc = acc[mi][ni];
            #pragma unroll
            for (int half = 0; half < 2; half++) {
                int r = gm + half * 8;
                if (r < M) {
                    #pragma unroll
                    for (int j = 0; j < 2; j++) {
                        int col = gn + j;
                        if (col < N) {
                            float v = cc[half * 2 + j];
                            if (EPI == 1)
                                v = fmaxf(v + aux[(size_t)r * N + col] + bias[col], 0.f);
                            C[(size_t)r * ldc + col] = v;
                        }
                    }
                }
            }
        }
    }
}

// ---------------- generic 32x32 tiled transpose ------------------------------
__global__ void transpose_k(const float* __restrict__ in, float* __restrict__ out,
                            int R, int C)
{
    __shared__ float tile[32][33];
    int c0 = blockIdx.x * 32, r0 = blockIdx.y * 32;
    int x = threadIdx.x, y = threadIdx.y;
    #pragma unroll
    for (int j = 0; j < 32; j += 8) {
        int r = r0 + y + j, c = c0 + x;
        tile[y + j][x] = (r < R && c < C) ? in[(size_t)r * C + c] : 0.f;
    }
    __syncthreads();
    #pragma unroll
    for (int j = 0; j < 32; j += 8) {
        int c = c0 + y + j, r = r0 + x;
        if (c < C && r < R) out[(size_t)c * R + r] = tile[x][y + j];
    }
}

// ---------------- instance-norm stats (2-stage) ------------------------------
__global__ void stats_part(const float* __restrict__ s, float* __restrict__ part)
{
    int x = blockIdx.x, b = blockIdx.y;
    const float4* p = (const float4*)(s + (size_t)b * NT + (size_t)x * 31500);
    float sum = 0.f, sq = 0.f;
    for (int i = threadIdx.x; i < 7875; i += 256) {
        float4 v = p[i];
        sum += v.x + v.y + v.z + v.w;
        sq  += v.x*v.x + v.y*v.y + v.z*v.z + v.w*v.w;
    }
    __shared__ float ssum[256], ssq[256];
    ssum[threadIdx.x] = sum; ssq[threadIdx.x] = sq;
    __syncthreads();
    for (int o = 128; o > 0; o >>= 1) {
        if (threadIdx.x < o) {
            ssum[threadIdx.x] += ssum[threadIdx.x + o];
            ssq[threadIdx.x]  += ssq[threadIdx.x + o];
        }
        __syncthreads();
    }
    if (threadIdx.x == 0) {
        part[(b * 4 + x) * 2 + 0] = ssum[0];
        part[(b * 4 + x) * 2 + 1] = ssq[0];
    }
}

__global__ void stats_comb(const float* __restrict__ part, float* __restrict__ mv)
{
    int b = threadIdx.x;
    if (b >= BB) return;
    float sum = 0.f, sq = 0.f;
    #pragma unroll
    for (int x = 0; x < 4; x++) {
        sum += part[(b * 4 + x) * 2 + 0];
        sq  += part[(b * 4 + x) * 2 + 1];
    }
    float m = sum / (float)NT;
    float var = sq / (float)NT - m * m;
    mv[2 * b] = m;
    mv[2 * b + 1] = rsqrtf(var + 1e-5f);
}

// ---------------- Sinkhorn v3: register E, SMEM-staged reductions, no SHFL ---
// 4-CTA cluster per batch; 512 threads; warp w holds rows {w+16j, j=0..6},
// lane l holds cols {64k+2l, 64k+2l+1, k=0..4}.
#define SK_THREADS 512
#define SK_NW 16
#define RPC 100
#define RTP 320            // stride for wacc/recv (multiple of 2, float2-safe)
#define STP 321            // stage stride (conflict-free transposed reads)
#define JMAX 7

#define OFF_V     0                       // 320 floats
#define OFF_U     320                     // 128 floats (100 used)
#define OFF_PACC  448                     // 100*33 = 3300
#define OFF_WACC  3748                    // 16*RTP = 5120
#define OFF_RECV  8868                    // 2*4*RTP = 2560
#define OFF_MBAR  11428                   // 4 floats = 2 mbarriers (byte 45712, 8B-aligned)
#define OFF_STAGE 11432                   // RPC*STP = 32100
#define SK_FLOATS (OFF_STAGE + RPC*STP)   // 43532
#define SK_SMEM  (SK_FLOATS*4)            // 174128 bytes

__global__ void __cluster_dims__(4, 1, 1) __launch_bounds__(SK_THREADS, 1)
sinkhorn_kernel(
    const float* __restrict__ s, const float* __restrict__ gamma,
    const float* __restrict__ beta, const float* __restrict__ mv,
    float* __restrict__ s1T)
{
    extern __shared__ float sm[];
    float* vS    = sm + OFF_V;
    float* uS    = sm + OFF_U;
    float* pacc  = sm + OFF_PACC;
    float* wacc  = sm + OFF_WACC;
    float* recv  = sm + OFF_RECV;
    float* stage = sm + OFF_STAGE;
    uint32_t mbar = smem_to_u32(sm + OFF_MBAR);

    int b = blockIdx.x >> 2;
    int rank = blockIdx.x & 3;
    int tid = threadIdx.x, wid = tid >> 5, lane = tid & 31;
    int rowbase = rank * RPC;

    if (tid == 0) { MBARRIER_INIT(mbar, 4); MBARRIER_INIT(mbar + 8, 4); }
    for (int c = tid; c < RTP; c += SK_THREADS) vS[c] = (c < TT) ? 1.f : 0.f;
    __syncthreads();
    // barriers + vS must be ready cluster-wide before first remote traffic
    asm volatile("barrier.cluster.arrive.aligned;" ::: "memory");
    asm volatile("barrier.cluster.wait.aligned;" ::: "memory");

    float m = mv[2 * b], rstd = mv[2 * b + 1];
    float g = gamma[0] * rstd, be = beta[0];
    const float* sb = s + (size_t)b * NT;

    // load E slab into registers: E[j][k] covers row (wid+16j), cols 64k+2lane(+1)
    float2 E[JMAX][5];
    #pragma unroll
    for (int j = 0; j < JMAX; j++) {
        int r = wid + 16 * j;
        bool rv = (r < RPC);
        const float* srow = sb + (size_t)(rowbase + (rv ? r : 0)) * TT;
        #pragma unroll
        for (int k = 0; k < 5; k++) {
            int c = 64 * k + 2 * lane;
            E[j][k].x = (rv && c     < TT) ? __expf(g * (srow[c]     - m) + be) : 0.f;
            E[j][k].y = (rv && c + 1 < TT) ? __expf(g * (srow[c + 1] - m) + be) : 0.f;
        }
    }

    for (int it = 0; it < 100; ++it) {
        int par = it & 1;

        // --- phase A: per-lane row partial dots -> pacc (no shuffles) -------
        {
            float2 vv[5];
            #pragma unroll
            for (int k = 0; k < 5; k++)
                vv[k] = *(const float2*)&vS[64 * k + 2 * lane];
            #pragma unroll
            for (int j = 0; j < JMAX; j++) {
                int r = wid + 16 * j;
                if (r < RPC) {
                    float d0 = 0.f, d1 = 0.f;
                    #pragma unroll
                    for (int k = 0; k < 5; k++) {
                        d0 = fmaf(E[j][k].x, vv[k].x, d0);
                        d1 = fmaf(E[j][k].y, vv[k].y, d1);
                    }
                    pacc[r * 33 + lane] = d0 + d1;
                }
            }
        }
        __syncthreads();

        // --- row sums: thread r sums 32 partials, u[r] = 1/dot --------------
        if (tid < RPC) {
            const float* pr = pacc + tid * 33;
            float s0 = 0.f, s1 = 0.f, s2 = 0.f, s3 = 0.f;
            #pragma unroll
            for (int i = 0; i < 32; i += 4) {
                s0 += pr[i]; s1 += pr[i + 1]; s2 += pr[i + 2]; s3 += pr[i + 3];
            }
            uS[tid] = __fdividef(1.f, (s0 + s1) + (s2 + s3));
        }
        __syncthreads();

        // --- phase B: per-warp column accumulation into wacc ----------------
        {
            float2 ca[5];
            #pragma unroll
            for (int k = 0; k < 5; k++) ca[k] = make_float2(0.f, 0.f);
            #pragma unroll
            for (int j = 0; j < JMAX; j++) {
                int r = wid + 16 * j;
                if (r < RPC) {
                    float uu = uS[r];   // broadcast read (same addr per warp)
                    #pragma unroll
                    for (int k = 0; k < 5; k++) {
                        ca[k].x = fmaf(uu, E[j][k].x, ca[k].x);
                        ca[k].y = fmaf(uu, E[j][k].y, ca[k].y);
                    }
                }
            }
            #pragma unroll
            for (int k = 0; k < 5; k++)
                *(float2*)&wacc[wid * RTP + 64 * k + 2 * lane] = ca[k];
        }
        __syncthreads();

        // --- 16-way column sum + DSMEM broadcast to all 4 cluster CTAs ------
        for (int c = tid; c < TT; c += SK_THREADS) {
            float p = 0.f;
            #pragma unroll
            for (int w = 0; w < SK_NW; w++) p += wacc[w * RTP + c];
            float* dst = recv + (par * 4 + rank) * RTP + c;
            uint32_t laddr = (uint32_t)__cvta_generic_to_shared(dst);
            #pragma unroll
            for (int cta = 0; cta < 4; cta++) {
                uint32_t raddr;
                asm volatile("mapa.shared::cluster.u32 %0, %1, %2;"
                             : "=r"(raddr) : "r"(laddr), "r"(cta));
                asm volatile("st.shared::cluster.f32 [%0], %1;"
                             :: "r"(raddr), "f"(p) : "memory");
            }
        }
        // make every thread's remote stores cluster-visible before the arrive
        asm volatile("fence.acq_rel.cluster;" ::: "memory");
        __syncthreads();
        if (tid == 0) {
            uint32_t lb = mbar + ((it & 1) << 3);
            #pragma unroll
            for (int cta = 0; cta < 4; cta++) MBAR_ARRIVE_REMOTE(lb, cta);
        }
        MBAR_WAIT_CLUSTER(mbar + ((it & 1) << 3), (it >> 1) & 1);

        // --- col phase: v = 1/(sum of 4 partials) ---------------------------
        for (int c = tid; c < TT; c += SK_THREADS) {
            float sum = recv[(par * 4 + 0) * RTP + c] + recv[(par * 4 + 1) * RTP + c]
                      + recv[(par * 4 + 2) * RTP + c] + recv[(par * 4 + 3) * RTP + c];
            vS[c] = __fdividef(1.f, sum);
        }
        __syncthreads();
    }

    // --- epilogue: stage = E*u, then transposed coalesced write * v ----------
    #pragma unroll
    for (int j = 0; j < JMAX; j++) {
        int r = wid + 16 * j;
        if (r < RPC) {
            float uu = uS[r];
            #pragma unroll
            for (int k = 0; k < 5; k++) {
                int c = 64 * k + 2 * lane;
                stage[r * STP + c]     = E[j][k].x * uu;
                stage[r * STP + c + 1] = E[j][k].y * uu;
            }
        }
    }
    __syncthreads();
    float* outp = s1T + (size_t)b * TT * NN;
    for (int t = wid; t < TT; t += SK_NW) {
        float vt = vS[t];
        #pragma unroll
        for (int jj = 0; jj < 4; jj++) {
            int n = lane + 32 * jj;
            if (n < RPC)
                outp[(size_t)t * NN + rowbase + n] = stage[n * STP + t] * vt;
        }
    }
}

// ---------------- final head: pred[bt] = dot(h[bt,:], Wo) + bo ---------------
__global__ void final_head(const float* __restrict__ h, const float* __restrict__ Wo,
                           const float* __restrict__ bo, float* __restrict__ out)
{
    int row = blockIdx.x * 8 + (threadIdx.x >> 5);
    int lane = threadIdx.x & 31;
    if (row >= BT) return;
    const float* hr = h + (size_t)row * HH;
    float acc = 0.f;
    #pragma unroll
    for (int k = 0; k < HH / 32; k++)
        acc += hr[lane + 32 * k] * Wo[lane + 32 * k];
    #pragma unroll
    for (int o = 16; o > 0; o >>= 1)
        acc += __shfl_xor_sync(0xffffffffu, acc, o);
    if (lane == 0) out[row] = acc + bo[0];
}

// ---------------- launcher ---------------------------------------------------
extern "C" void kernel_launch(void* const* d_in, const int* in_sizes, int n_in,
                              void* d_out, int out_size)
{
    const float* features = (const float*)d_in[0];
    const float* text     = (const float*)d_in[1];
    const float* Amat     = (const float*)d_in[2];
    const float* gamma    = (const float*)d_in[3];
    const float* beta     = (const float*)d_in[4];
    const float* Wh       = (const float*)d_in[5];
    const float* bh       = (const float*)d_in[6];
    const float* Wo       = (const float*)d_in[7];
    const float* bo       = (const float*)d_in[8];
    float* out = (float*)d_out;

    float *WhT, *TAT, *S, *txh, *mv, *part, *FWT, *s1T, *Hb;
    cudaGetSymbolAddress((void**)&WhT,  g_WhT);
    cudaGetSymbolAddress((void**)&TAT,  g_TAT);
    cudaGetSymbolAddress((void**)&S,    g_S);
    cudaGetSymbolAddress((void**)&txh,  g_txh);
    cudaGetSymbolAddress((void**)&mv,   g_mv);
    cudaGetSymbolAddress((void**)&part, g_part);
    cudaGetSymbolAddress((void**)&FWT,  g_FWT);
    cudaGetSymbolAddress((void**)&s1T,  g_s1T);
    cudaGetSymbolAddress((void**)&Hb,   g_H);

    cudaFuncSetAttribute(sinkhorn_kernel,
                         cudaFuncAttributeMaxDynamicSharedMemorySize, SK_SMEM);
    cudaFuncSetAttribute(hgemm<0>,
                         cudaFuncAttributeMaxDynamicSharedMemorySize, HG_SMEM);
    cudaFuncSetAttribute(hgemm<1>,
                         cudaFuncAttributeMaxDynamicSharedMemorySize, HG_SMEM);

    // fork a side stream for the Wh-dependent branch
    cudaStream_t s1;
    cudaStreamCreateWithFlags(&s1, cudaStreamNonBlocking);
    cudaEvent_t e0, e1;
    cudaEventCreateWithFlags(&e0, cudaEventDisableTiming);
    cudaEventCreateWithFlags(&e1, cudaEventDisableTiming);
    cudaEventRecord(e0, 0);
    cudaStreamWaitEvent(s1, e0, 0);

    // ---- side branch (stream s1): WhT -> txh, FWT ----
    transpose_k<<<dim3(8, 32, 1), dim3(32, 8), 0, s1>>>(Wh, WhT, 2 * DD, HH);
    hgemm<0><<<dim3(4, 3, 1), 256, HG_SMEM, s1>>>(TT, HH, DD,
        text, DD, 0, WhT + DD, 2 * DD, 0, txh, HH, 0, nullptr, nullptr);
    hgemm<0><<<dim3(7, 2, BB), 256, HG_SMEM, s1>>>(HH, NN, DD,
        WhT, 2 * DD, 0,
        features, DD, (long long)NN * DD,
        FWT, NN, (long long)HH * NN, nullptr, nullptr);
    cudaEventRecord(e1, s1);

    // ---- main branch (stream 0): TAT -> S -> stats -> sinkhorn ----
    hgemm<0><<<dim3(8, 3, 1), 256, HG_SMEM>>>(TT, DD, DD,
        text, DD, 0, Amat, DD, 0, TAT, DD, 0, nullptr, nullptr);
    hgemm<0><<<dim3(5, 100, 1), 256, HG_SMEM>>>(BB * NN, TT, DD,
        features, DD, 0, TAT, DD, 0, S, TT, 0, nullptr, nullptr);
    stats_part<<<dim3(4, BB), 256>>>(S, part);
    stats_comb<<<1, 32>>>(part, mv);
    sinkhorn_kernel<<<BB * 4, SK_THREADS, SK_SMEM>>>(S, gamma, beta, mv, s1T);

    // join, then head
    cudaStreamWaitEvent(0, e1, 0);
    hgemm<1><<<dim3(4, 3, BB), 256, HG_SMEM>>>(TT, HH, NN,
        s1T, NN, (long long)TT * NN,
        FWT, NN, (long long)HH * NN,
        Hb,  HH, (long long)TT * HH, txh, bh);
    final_head<<<1260, 256>>>(Hb, Wo, bo, out);

    cudaEventDestroy(e0);
    cudaEventDestroy(e1);
    cudaStreamDestroy(s1);
}